// round 9
// baseline (speedup 1.0000x reference)
#include <cuda_runtime.h>
#include <cuda_fp16.h>
#include <stdint.h>

#define NROWS 32768   // M
#define KCOLS 4096    // GEMM N (codebook entries)
#define DDIM  512     // reduction K

#define BM 128
#define BN 128
#define BK 64                    // 64 fp16 = 128B rows (SW128-native)
#define NTILES (DDIM / BK)       // 8
#define NXTILES (KCOLS / BN)     // 32
#define NTHREADS 256
#define NSTAGES 3

#define A_BYTES (BM * BK * 2)               // 16384
#define B_BYTES (BN * BK * 2)               // 16384
#define STAGE_BYTES (A_BYTES + B_BYTES)     // 32768
#define SMEM_TOTAL (NSTAGES * STAGE_BYTES)  // 98304 (2 CTAs/SM: 196KB <= 228KB)

// fp16 copies of the operands (written by convert kernel each launch)
__device__ __half g_A16[NROWS * DDIM];   // 32 MB
__device__ __half g_B16[KCOLS * DDIM];   // 4 MB

// per-(row, N-tile) max of fp16-path logits, orderable uint. 4MB. Fully
// rewritten by the GEMM epilogue every launch -> no init needed.
__device__ unsigned int g_tilemax[NROWS * NXTILES];

__device__ __forceinline__ uint32_t smem_u32(const void* p) {
    uint32_t a;
    asm("{ .reg .u64 t; cvta.to.shared.u64 t, %1; cvt.u32.u64 %0, t; }" : "=r"(a) : "l"(p));
    return a;
}
__device__ __forceinline__ uint32_t swz(uint32_t off) {   // SW128
    return off ^ ((off >> 3) & 0x70);
}

#define CP_ASYNC16(dst, src) \
    asm volatile("cp.async.cg.shared.global [%0], [%1], 16;" :: "r"(dst), "l"(src) : "memory")

#define LDSM4(r0, r1, r2, r3, addr) \
    asm volatile("ldmatrix.sync.aligned.m8n8.x4.shared.b16 {%0,%1,%2,%3}, [%4];" \
        : "=r"(r0), "=r"(r1), "=r"(r2), "=r"(r3) : "r"(addr))

__device__ __forceinline__ void mma_f16(float* d, const uint32_t* a, const uint32_t* b) {
    asm volatile(
        "mma.sync.aligned.m16n8k16.row.col.f32.f16.f16.f32 "
        "{%0,%1,%2,%3}, {%4,%5,%6,%7}, {%8,%9}, {%0,%1,%2,%3};"
        : "+f"(d[0]), "+f"(d[1]), "+f"(d[2]), "+f"(d[3])
        : "r"(a[0]), "r"(a[1]), "r"(a[2]), "r"(a[3]), "r"(b[0]), "r"(b[1]));
}

__device__ __forceinline__ unsigned int float_orderable(float f) {
    unsigned int b = __float_as_uint(f);
    return (b & 0x80000000u) ? ~b : (b | 0x80000000u);
}
__device__ __forceinline__ float orderable_to_float(unsigned int u) {
    return (u & 0x80000000u) ? __uint_as_float(u ^ 0x80000000u) : __uint_as_float(~u);
}

// ---------------------------------------------------------------------------
// fused fp32 -> fp16 conversion of both operands (grid-stride, 8 elems/iter)
// ---------------------------------------------------------------------------
#define A8 (NROWS * DDIM / 8)
#define B8 (KCOLS * DDIM / 8)
__global__ __launch_bounds__(256)
void convert_kernel(const float* __restrict__ srcA, const float* __restrict__ srcB) {
    for (int i = blockIdx.x * blockDim.x + threadIdx.x; i < A8 + B8;
         i += gridDim.x * blockDim.x) {
        const float4* s4;
        uint4* d4;
        if (i < A8) {
            s4 = reinterpret_cast<const float4*>(srcA) + (size_t)i * 2;
            d4 = reinterpret_cast<uint4*>(g_A16) + i;
        } else {
            s4 = reinterpret_cast<const float4*>(srcB) + (size_t)(i - A8) * 2;
            d4 = reinterpret_cast<uint4*>(g_B16) + (i - A8);
        }
        float4 v0 = s4[0], v1 = s4[1];
        __half2 h[4];
        h[0] = __floats2half2_rn(v0.x, v0.y);
        h[1] = __floats2half2_rn(v0.z, v0.w);
        h[2] = __floats2half2_rn(v1.x, v1.y);
        h[3] = __floats2half2_rn(v1.z, v1.w);
        *d4 = *reinterpret_cast<uint4*>(h);
    }
}

// ---------------------------------------------------------------------------
// fp16 tensor-core GEMM: C[NROWS, KCOLS] = A[NROWS, DDIM] * B[KCOLS, DDIM]^T
// CTA 128x128, 8 warps as 2(M) x 4(N), warp tile 64x32, fp32 accum.
// 3-stage cp.async pipeline, 2 CTAs/SM. Epilogue reduces per-row tile maxima.
// ---------------------------------------------------------------------------
__global__ __launch_bounds__(NTHREADS, 2)
void gemm_tc_kernel(float* __restrict__ C)
{
    extern __shared__ char smem[];
    __shared__ unsigned int sMax[BM];
    const uint32_t smem_base = smem_u32(smem);
    const int tid = threadIdx.x;
    const int lane = tid & 31;
    const int wid = tid >> 5;
    const int wy = wid >> 2;     // 0..1 : M offset wy*64
    const int wx = wid & 3;      // 0..3 : N offset wx*32
    const int bx = blockIdx.x;   // N tile
    const int by = blockIdx.y;   // M tile

    if (tid < BM) sMax[tid] = 0u;

    const __half* Ab = g_A16 + (size_t)by * BM * DDIM;
    const __half* Bb = g_B16 + (size_t)bx * BN * DDIM;

    const int lrow = tid >> 3;        // 0..31
    const int lc16 = (tid & 7) * 16;  // byte col within 128B row

    float acc[4][4][4];
#pragma unroll
    for (int i = 0; i < 4; i++)
#pragma unroll
        for (int j = 0; j < 4; j++)
#pragma unroll
            for (int q = 0; q < 4; q++) acc[i][j][q] = 0.0f;

    const int rl  = lane & 7;
    const int sel = lane >> 3;
    const int a_row_off = (sel & 1) * 8 + rl;
    const int a_colb    = (sel >> 1) * 16;
    const int b_row_off = (sel >> 1) * 8 + rl;
    const int b_colb    = (sel & 1) * 16;

    auto load_tile = [&](int t) {
        const int s = t % NSTAGES;
        const uint32_t sa = smem_base + s * STAGE_BYTES;
        const uint32_t sb = sa + A_BYTES;
        const int d0 = t * BK;
#pragma unroll
        for (int k = 0; k < 4; k++) {
            int r = lrow + k * 32;
            uint32_t off = swz((uint32_t)(r * 128 + lc16));
            CP_ASYNC16(sa + off, Ab + (size_t)r * DDIM + d0 + (lc16 >> 1));
            CP_ASYNC16(sb + off, Bb + (size_t)r * DDIM + d0 + (lc16 >> 1));
        }
        asm volatile("cp.async.commit_group;" ::: "memory");
    };

    load_tile(0);
    load_tile(1);

    for (int t = 0; t < NTILES; t++) {
        if (t < NTILES - 1) asm volatile("cp.async.wait_group 1;" ::: "memory");
        else                asm volatile("cp.async.wait_group 0;" ::: "memory");
        __syncthreads();
        // stage (t+2)%3 == stage (t-1)%3, freed by the barrier after compute(t-1)
        if (t + 2 < NTILES) load_tile(t + 2);

        const int s = t % NSTAGES;
        const uint32_t sa = smem_base + s * STAGE_BYTES;
        const uint32_t sb = sa + A_BYTES;

#pragma unroll
        for (int ks = 0; ks < 4; ks++) {        // k step = 16 fp16 = 32B
            const int k0b = ks * 32;
            uint32_t af[4][4], bf[4][2];
#pragma unroll
            for (int mt = 0; mt < 4; mt++) {
                uint32_t off = (uint32_t)((wy * 64 + mt * 16 + a_row_off) * 128 +
                                          k0b + a_colb);
                LDSM4(af[mt][0], af[mt][1], af[mt][2], af[mt][3], sa + swz(off));
            }
#pragma unroll
            for (int p = 0; p < 2; p++) {
                uint32_t off = (uint32_t)((wx * 32 + p * 16 + b_row_off) * 128 +
                                          k0b + b_colb);
                uint32_t r0, r1, r2, r3;
                LDSM4(r0, r1, r2, r3, sb + swz(off));
                bf[p * 2][0] = r0;     bf[p * 2][1] = r1;
                bf[p * 2 + 1][0] = r2; bf[p * 2 + 1][1] = r3;
            }
#pragma unroll
            for (int mt = 0; mt < 4; mt++)
#pragma unroll
                for (int nt = 0; nt < 4; nt++)
                    mma_f16(acc[mt][nt], af[mt], bf[nt]);
        }
        __syncthreads();
    }

    // ---- epilogue: write logits + per-row tile max ----
    const int row_base = by * BM + wy * 64 + (lane >> 2);
    const int col_base = bx * BN + wx * 32 + (lane & 3) * 2;
#pragma unroll
    for (int mt = 0; mt < 4; mt++) {
        int r0 = row_base + mt * 16;
        float* C0 = C + (size_t)r0 * KCOLS + col_base;
        float* C1 = C + (size_t)(r0 + 8) * KCOLS + col_base;
        float mx0 = -3.4e38f, mx1 = -3.4e38f;
#pragma unroll
        for (int nt = 0; nt < 4; nt++) {
            *reinterpret_cast<float2*>(C0 + nt * 8) =
                make_float2(acc[mt][nt][0], acc[mt][nt][1]);
            *reinterpret_cast<float2*>(C1 + nt * 8) =
                make_float2(acc[mt][nt][2], acc[mt][nt][3]);
            mx0 = fmaxf(mx0, fmaxf(acc[mt][nt][0], acc[mt][nt][1]));
            mx1 = fmaxf(mx1, fmaxf(acc[mt][nt][2], acc[mt][nt][3]));
        }
        mx0 = fmaxf(mx0, __shfl_xor_sync(0xffffffffu, mx0, 1));
        mx0 = fmaxf(mx0, __shfl_xor_sync(0xffffffffu, mx0, 2));
        mx1 = fmaxf(mx1, __shfl_xor_sync(0xffffffffu, mx1, 1));
        mx1 = fmaxf(mx1, __shfl_xor_sync(0xffffffffu, mx1, 2));
        if ((lane & 3) == 0) {
            int rl0 = wy * 64 + mt * 16 + (lane >> 2);
            atomicMax(&sMax[rl0],     float_orderable(mx0));
            atomicMax(&sMax[rl0 + 8], float_orderable(mx1));
        }
    }
    __syncthreads();
    if (tid < BM)
        g_tilemax[(size_t)(by * BM + tid) * NXTILES + bx] = sMax[tid];
}

// ---------------------------------------------------------------------------
// Exact argmax from tile maxima: select near-max tiles, load only those
// logits, recompute candidates exactly in fp32. One warp per row.
// ---------------------------------------------------------------------------
__global__ __launch_bounds__(256)
void argmax_kernel(const float* __restrict__ A, const float* __restrict__ B,
                   const float* __restrict__ C, float* __restrict__ out_idx)
{
    const int n = (blockIdx.x * blockDim.x + threadIdx.x) >> 5;   // row per warp
    const int lane = threadIdx.x & 31;
    if (n >= NROWS) return;

    // lane t holds tile t's max (NXTILES == 32)
    const unsigned int tm = g_tilemax[(size_t)n * NXTILES + lane];
    unsigned int gm = tm;
#pragma unroll
    for (int off = 16; off; off >>= 1)
        gm = max(gm, __shfl_xor_sync(0xffffffffu, gm, off));

    const float fmx = orderable_to_float(gm);
    const float thr = fmx - 5e-4f;                 // >> 8x worst-case fp16 error
    const unsigned int thr_ord = float_orderable(thr);

    unsigned int tilemask = __ballot_sync(0xffffffffu, tm >= thr_ord);

    const float4* Crow = reinterpret_cast<const float4*>(C + (size_t)n * KCOLS);
    int cand[8];
    int nc = 0;
    while (tilemask) {
        int tile = __ffs(tilemask) - 1;
        tilemask &= tilemask - 1;
        float4 v = Crow[tile * 32 + lane];
        int c0 = tile * BN + lane * 4;
        if (v.x >= thr && nc < 8) cand[nc++] = c0;
        if (v.y >= thr && nc < 8) cand[nc++] = c0 + 1;
        if (v.z >= thr && nc < 8) cand[nc++] = c0 + 2;
        if (v.w >= thr && nc < 8) cand[nc++] = c0 + 3;
    }

    // exact fp32 recompute of all candidates (warp-cooperative dots)
    const float4* z4 = reinterpret_cast<const float4*>(A + (size_t)n * DDIM) + lane * 4;
    unsigned long long best = 0ULL;

    for (int l = 0; l < 32; l++) {
        int cnt = __shfl_sync(0xffffffffu, nc, l);
        for (int j = 0; j < cnt; j++) {
            int mycol = (j < 8) ? cand[j] : 0;
            int col = __shfl_sync(0xffffffffu, mycol, l);
            const float4* c4 = reinterpret_cast<const float4*>(B + (size_t)col * DDIM) + lane * 4;
            float sum = 0.0f;
#pragma unroll
            for (int q = 0; q < 4; q++) {
                float4 a = z4[q], b = c4[q];
                sum = fmaf(a.x, b.x, sum);
                sum = fmaf(a.y, b.y, sum);
                sum = fmaf(a.z, b.z, sum);
                sum = fmaf(a.w, b.w, sum);
            }
#pragma unroll
            for (int off = 16; off; off >>= 1)
                sum += __shfl_xor_sync(0xffffffffu, sum, off);
            unsigned long long p = ((unsigned long long)float_orderable(sum) << 32) |
                                   (unsigned int)(KCOLS - 1 - col);   // lower col wins ties
            if (p > best) best = p;
        }
    }
    if (lane == 0)
        out_idx[n] = (float)(KCOLS - 1 - (unsigned int)(best & 0xFFFFFFFFu));
}

extern "C" void kernel_launch(void* const* d_in, const int* in_sizes, int n_in,
                              void* d_out, int out_size) {
    const float* z_e_x    = (const float*)d_in[0];  // [NROWS, DDIM]
    const float* codebook = (const float*)d_in[1];  // [KCOLS, DDIM]
    float* out = (float*)d_out;                      // logits then indices

    cudaFuncSetAttribute(gemm_tc_kernel, cudaFuncAttributeMaxDynamicSharedMemorySize, SMEM_TOTAL);

    convert_kernel<<<1184, 256>>>(z_e_x, codebook);   // 148 SMs * 8 blocks

    dim3 grid(KCOLS / BN, NROWS / BM);   // (32, 256), x fastest -> A-tile L2 reuse
    gemm_tc_kernel<<<grid, NTHREADS, SMEM_TOTAL>>>(out);

    long long logits_elems = (long long)NROWS * KCOLS;
    if ((long long)out_size >= logits_elems + NROWS) {
        argmax_kernel<<<NROWS / 8, 256>>>(z_e_x, codebook, out, out + logits_elems);
    }
}

// round 11
// speedup vs baseline: 1.0213x; 1.0213x over previous
#include <cuda_runtime.h>
#include <cuda_fp16.h>
#include <stdint.h>

#define NROWS 32768   // M
#define KCOLS 4096    // GEMM N (codebook entries)
#define DDIM  512     // reduction K

#define BM 128
#define BN 128
#define BK 64                    // 64 fp16 = 128B rows (SW128-native)
#define NTILES (DDIM / BK)       // 8
#define NXTILES (KCOLS / BN)     // 32
#define NTHREADS 128             // 4 warps: 2(M) x 2(N), warp tile 64x64
#define NSTAGES 3

#define A_BYTES (BM * BK * 2)               // 16384
#define B_BYTES (BN * BK * 2)               // 16384
#define STAGE_BYTES (A_BYTES + B_BYTES)     // 32768
#define SMEM_TOTAL (NSTAGES * STAGE_BYTES)  // 98304; occ 2 -> 192KB <= 228KB

// fp16 copies of the operands (written by convert kernel each launch)
__device__ __half g_A16[NROWS * DDIM];   // 32 MB
__device__ __half g_B16[KCOLS * DDIM];   // 4 MB

// per-(row, N-tile) max of fp16-path logits, orderable uint. 4MB. Fully
// rewritten by the GEMM epilogue every launch -> no init needed.
__device__ unsigned int g_tilemax[NROWS * NXTILES];

__device__ __forceinline__ uint32_t smem_u32(const void* p) {
    uint32_t a;
    asm("{ .reg .u64 t; cvta.to.shared.u64 t, %1; cvt.u32.u64 %0, t; }" : "=r"(a) : "l"(p));
    return a;
}
__device__ __forceinline__ uint32_t swz(uint32_t off) {   // SW128
    return off ^ ((off >> 3) & 0x70);
}

#define CP_ASYNC16(dst, src) \
    asm volatile("cp.async.cg.shared.global [%0], [%1], 16;" :: "r"(dst), "l"(src) : "memory")

#define LDSM4(r0, r1, r2, r3, addr) \
    asm volatile("ldmatrix.sync.aligned.m8n8.x4.shared.b16 {%0,%1,%2,%3}, [%4];" \
        : "=r"(r0), "=r"(r1), "=r"(r2), "=r"(r3) : "r"(addr))

__device__ __forceinline__ void mma_f16(float* d, const uint32_t* a, const uint32_t* b) {
    asm volatile(
        "mma.sync.aligned.m16n8k16.row.col.f32.f16.f16.f32 "
        "{%0,%1,%2,%3}, {%4,%5,%6,%7}, {%8,%9}, {%0,%1,%2,%3};"
        : "+f"(d[0]), "+f"(d[1]), "+f"(d[2]), "+f"(d[3])
        : "r"(a[0]), "r"(a[1]), "r"(a[2]), "r"(a[3]), "r"(b[0]), "r"(b[1]));
}

__device__ __forceinline__ unsigned int float_orderable(float f) {
    unsigned int b = __float_as_uint(f);
    return (b & 0x80000000u) ? ~b : (b | 0x80000000u);
}
__device__ __forceinline__ float orderable_to_float(unsigned int u) {
    return (u & 0x80000000u) ? __uint_as_float(u ^ 0x80000000u) : __uint_as_float(~u);
}

// ---------------------------------------------------------------------------
// fused fp32 -> fp16 conversion of both operands (grid-stride, 8 elems/iter)
// ---------------------------------------------------------------------------
#define A8 (NROWS * DDIM / 8)
#define B8 (KCOLS * DDIM / 8)
__global__ __launch_bounds__(256)
void convert_kernel(const float* __restrict__ srcA, const float* __restrict__ srcB) {
    for (int i = blockIdx.x * blockDim.x + threadIdx.x; i < A8 + B8;
         i += gridDim.x * blockDim.x) {
        const float4* s4;
        uint4* d4;
        if (i < A8) {
            s4 = reinterpret_cast<const float4*>(srcA) + (size_t)i * 2;
            d4 = reinterpret_cast<uint4*>(g_A16) + i;
        } else {
            s4 = reinterpret_cast<const float4*>(srcB) + (size_t)(i - A8) * 2;
            d4 = reinterpret_cast<uint4*>(g_B16) + (i - A8);
        }
        float4 v0 = s4[0], v1 = s4[1];
        __half2 h[4];
        h[0] = __floats2half2_rn(v0.x, v0.y);
        h[1] = __floats2half2_rn(v0.z, v0.w);
        h[2] = __floats2half2_rn(v1.x, v1.y);
        h[3] = __floats2half2_rn(v1.z, v1.w);
        *d4 = *reinterpret_cast<uint4*>(h);
    }
}

// ---------------------------------------------------------------------------
// fp16 tensor-core GEMM: C[NROWS, KCOLS] = A[NROWS, DDIM] * B[KCOLS, DDIM]^T
// CTA 128x128, 4 warps as 2(M) x 2(N), warp tile 64x64, fp32 accum.
// 3-stage cp.async pipeline, 2 CTAs/SM.
// ---------------------------------------------------------------------------
__global__ __launch_bounds__(NTHREADS, 2)
void gemm_tc_kernel(float* __restrict__ C)
{
    extern __shared__ char smem[];
    __shared__ unsigned int sMax[BM];
    const uint32_t smem_base = smem_u32(smem);
    const int tid = threadIdx.x;
    const int lane = tid & 31;
    const int wid = tid >> 5;
    const int wy = wid >> 1;     // 0..1 : M offset wy*64
    const int wx = wid & 1;      // 0..1 : N offset wx*64
    const int bx = blockIdx.x;   // N tile
    const int by = blockIdx.y;   // M tile

    sMax[tid] = 0u;

    const __half* Ab = g_A16 + (size_t)by * BM * DDIM;
    const __half* Bb = g_B16 + (size_t)bx * BN * DDIM;

    // loader: each operand tile = 1024 x 16B chunks; 128 threads x 8
    const int lrow = tid >> 3;        // 0..15
    const int lc16 = (tid & 7) * 16;  // byte col within 128B row

    float acc[4][8][4];
#pragma unroll
    for (int i = 0; i < 4; i++)
#pragma unroll
        for (int j = 0; j < 8; j++)
#pragma unroll
            for (int q = 0; q < 4; q++) acc[i][j][q] = 0.0f;

    const int rl  = lane & 7;
    const int sel = lane >> 3;
    const int a_row_off = (sel & 1) * 8 + rl;
    const int a_colb    = (sel >> 1) * 16;
    const int b_row_off = (sel >> 1) * 8 + rl;
    const int b_colb    = (sel & 1) * 16;

    auto load_tile = [&](int t) {
        const int s = t % NSTAGES;
        const uint32_t sa = smem_base + s * STAGE_BYTES;
        const uint32_t sb = sa + A_BYTES;
        const int d0 = t * BK;
#pragma unroll
        for (int k = 0; k < 8; k++) {
            int r = lrow + k * 16;
            uint32_t off = swz((uint32_t)(r * 128 + lc16));
            CP_ASYNC16(sa + off, Ab + (size_t)r * DDIM + d0 + (lc16 >> 1));
            CP_ASYNC16(sb + off, Bb + (size_t)r * DDIM + d0 + (lc16 >> 1));
        }
        asm volatile("cp.async.commit_group;" ::: "memory");
    };

    load_tile(0);
    load_tile(1);

    for (int t = 0; t < NTILES; t++) {
        if (t < NTILES - 1) asm volatile("cp.async.wait_group 1;" ::: "memory");
        else                asm volatile("cp.async.wait_group 0;" ::: "memory");
        __syncthreads();
        if (t + 2 < NTILES) load_tile(t + 2);

        const int s = t % NSTAGES;
        const uint32_t sa = smem_base + s * STAGE_BYTES;
        const uint32_t sb = sa + A_BYTES;

#pragma unroll
        for (int ks = 0; ks < 4; ks++) {        // k step = 16 fp16 = 32B
            const int k0b = ks * 32;
            uint32_t af[4][4], bf[8][2];
#pragma unroll
            for (int mt = 0; mt < 4; mt++) {
                uint32_t off = (uint32_t)((wy * 64 + mt * 16 + a_row_off) * 128 +
                                          k0b + a_colb);
                LDSM4(af[mt][0], af[mt][1], af[mt][2], af[mt][3], sa + swz(off));
            }
#pragma unroll
            for (int p = 0; p < 4; p++) {
                uint32_t off = (uint32_t)((wx * 64 + p * 16 + b_row_off) * 128 +
                                          k0b + b_colb);
                uint32_t r0, r1, r2, r3;
                LDSM4(r0, r1, r2, r3, sb + swz(off));
                bf[p * 2][0] = r0;     bf[p * 2][1] = r1;
                bf[p * 2 + 1][0] = r2; bf[p * 2 + 1][1] = r3;
            }
#pragma unroll
            for (int mt = 0; mt < 4; mt++)
#pragma unroll
                for (int nt = 0; nt < 8; nt++)
                    mma_f16(acc[mt][nt], af[mt], bf[nt]);
        }
        __syncthreads();
    }

    // ---- epilogue: write logits + per-row tile max ----
    const int row_base = by * BM + wy * 64 + (lane >> 2);
    const int col_base = bx * BN + wx * 64 + (lane & 3) * 2;
#pragma unroll
    for (int mt = 0; mt < 4; mt++) {
        int r0 = row_base + mt * 16;
        float* C0 = C + (size_t)r0 * KCOLS + col_base;
        float* C1 = C + (size_t)(r0 + 8) * KCOLS + col_base;
        float mx0 = -3.4e38f, mx1 = -3.4e38f;
#pragma unroll
        for (int nt = 0; nt < 8; nt++) {
            *reinterpret_cast<float2*>(C0 + nt * 8) =
                make_float2(acc[mt][nt][0], acc[mt][nt][1]);
            *reinterpret_cast<float2*>(C1 + nt * 8) =
                make_float2(acc[mt][nt][2], acc[mt][nt][3]);
            mx0 = fmaxf(mx0, fmaxf(acc[mt][nt][0], acc[mt][nt][1]));
            mx1 = fmaxf(mx1, fmaxf(acc[mt][nt][2], acc[mt][nt][3]));
        }
        mx0 = fmaxf(mx0, __shfl_xor_sync(0xffffffffu, mx0, 1));
        mx0 = fmaxf(mx0, __shfl_xor_sync(0xffffffffu, mx0, 2));
        mx1 = fmaxf(mx1, __shfl_xor_sync(0xffffffffu, mx1, 1));
        mx1 = fmaxf(mx1, __shfl_xor_sync(0xffffffffu, mx1, 2));
        if ((lane & 3) == 0) {
            int rl0 = wy * 64 + mt * 16 + (lane >> 2);
            atomicMax(&sMax[rl0],     float_orderable(mx0));
            atomicMax(&sMax[rl0 + 8], float_orderable(mx1));
        }
    }
    __syncthreads();
    g_tilemax[(size_t)(by * BM + tid) * NXTILES + bx] = sMax[tid];
}

// ---------------------------------------------------------------------------
// Exact argmax from tile maxima: select near-max tiles, load only those
// logits, recompute candidates exactly in fp32. One warp per row.
// ---------------------------------------------------------------------------
__global__ __launch_bounds__(256)
void argmax_kernel(const float* __restrict__ A, const float* __restrict__ B,
                   const float* __restrict__ C, float* __restrict__ out_idx)
{
    const int n = (blockIdx.x * blockDim.x + threadIdx.x) >> 5;   // row per warp
    const int lane = threadIdx.x & 31;
    if (n >= NROWS) return;

    // lane t holds tile t's max (NXTILES == 32)
    const unsigned int tm = g_tilemax[(size_t)n * NXTILES + lane];
    unsigned int gm = tm;
#pragma unroll
    for (int off = 16; off; off >>= 1)
        gm = max(gm, __shfl_xor_sync(0xffffffffu, gm, off));

    const float fmx = orderable_to_float(gm);
    const float thr = fmx - 5e-4f;                 // >> 8x worst-case fp16 error
    const unsigned int thr_ord = float_orderable(thr);

    unsigned int tilemask = __ballot_sync(0xffffffffu, tm >= thr_ord);

    const float4* Crow = reinterpret_cast<const float4*>(C + (size_t)n * KCOLS);
    int cand[8];
    int nc = 0;
    while (tilemask) {
        int tile = __ffs(tilemask) - 1;
        tilemask &= tilemask - 1;
        float4 v = Crow[tile * 32 + lane];
        int c0 = tile * BN + lane * 4;
        if (v.x >= thr && nc < 8) cand[nc++] = c0;
        if (v.y >= thr && nc < 8) cand[nc++] = c0 + 1;
        if (v.z >= thr && nc < 8) cand[nc++] = c0 + 2;
        if (v.w >= thr && nc < 8) cand[nc++] = c0 + 3;
    }

    // exact fp32 recompute of all candidates (warp-cooperative dots)
    const float4* z4 = reinterpret_cast<const float4*>(A + (size_t)n * DDIM) + lane * 4;
    unsigned long long best = 0ULL;

    for (int l = 0; l < 32; l++) {
        int cnt = __shfl_sync(0xffffffffu, nc, l);
        for (int j = 0; j < cnt; j++) {
            int mycol = (j < 8) ? cand[j] : 0;
            int col = __shfl_sync(0xffffffffu, mycol, l);
            const float4* c4 = reinterpret_cast<const float4*>(B + (size_t)col * DDIM) + lane * 4;
            float sum = 0.0f;
#pragma unroll
            for (int q = 0; q < 4; q++) {
                float4 a = z4[q], b = c4[q];
                sum = fmaf(a.x, b.x, sum);
                sum = fmaf(a.y, b.y, sum);
                sum = fmaf(a.z, b.z, sum);
                sum = fmaf(a.w, b.w, sum);
            }
#pragma unroll
            for (int off = 16; off; off >>= 1)
                sum += __shfl_xor_sync(0xffffffffu, sum, off);
            unsigned long long p = ((unsigned long long)float_orderable(sum) << 32) |
                                   (unsigned int)(KCOLS - 1 - col);   // lower col wins ties
            if (p > best) best = p;
        }
    }
    if (lane == 0)
        out_idx[n] = (float)(KCOLS - 1 - (unsigned int)(best & 0xFFFFFFFFu));
}

extern "C" void kernel_launch(void* const* d_in, const int* in_sizes, int n_in,
                              void* d_out, int out_size) {
    const float* z_e_x    = (const float*)d_in[0];  // [NROWS, DDIM]
    const float* codebook = (const float*)d_in[1];  // [KCOLS, DDIM]
    float* out = (float*)d_out;                      // logits then indices

    cudaFuncSetAttribute(gemm_tc_kernel, cudaFuncAttributeMaxDynamicSharedMemorySize, SMEM_TOTAL);

    convert_kernel<<<1184, 256>>>(z_e_x, codebook);   // 148 SMs * 8 blocks

    dim3 grid(KCOLS / BN, NROWS / BM);   // (32, 256), x fastest -> A-tile L2 reuse
    gemm_tc_kernel<<<grid, NTHREADS, SMEM_TOTAL>>>(out);

    long long logits_elems = (long long)NROWS * KCOLS;
    if ((long long)out_size >= logits_elems + NROWS) {
        argmax_kernel<<<NROWS / 8, 256>>>(z_e_x, codebook, out, out + logits_elems);
    }
}

// round 12
// speedup vs baseline: 1.0354x; 1.0139x over previous
#include <cuda_runtime.h>
#include <cuda_fp16.h>
#include <stdint.h>

#define NROWS 32768   // M
#define KCOLS 4096    // GEMM N (codebook entries)
#define DDIM  512     // reduction K

#define BM 128
#define BN 128
#define BK 64                    // 64 fp16 = 128B rows (SW128-native)
#define NTILES (DDIM / BK)       // 8
#define NXTILES (KCOLS / BN)     // 32
#define NTHREADS 128             // 4 warps: 2(M) x 2(N), warp tile 64x64
#define NSTAGES 3

#define BSCALE 4096.0f           // 2^12: lifts codebook out of fp16 subnormals
#define BSCALE_INV (1.0f / 4096.0f)

#define A_BYTES (BM * BK * 2)               // 16384
#define B_BYTES (BN * BK * 2)               // 16384
#define STAGE_BYTES (A_BYTES + B_BYTES)     // 32768
#define SMEM_TOTAL (NSTAGES * STAGE_BYTES)  // 98304; occ 2 -> 192KB <= 228KB

// fp16 copies of the operands (written by convert kernel each launch)
__device__ __half g_A16[NROWS * DDIM];   // 32 MB
__device__ __half g_B16[KCOLS * DDIM];   // 4 MB (scaled by BSCALE)

// per-(row, N-tile) max of fp16-path logits, orderable uint. 4MB. Fully
// rewritten by the GEMM epilogue every launch -> no init needed.
__device__ unsigned int g_tilemax[NROWS * NXTILES];

__device__ __forceinline__ uint32_t smem_u32(const void* p) {
    uint32_t a;
    asm("{ .reg .u64 t; cvta.to.shared.u64 t, %1; cvt.u32.u64 %0, t; }" : "=r"(a) : "l"(p));
    return a;
}
__device__ __forceinline__ uint32_t swz(uint32_t off) {   // SW128
    return off ^ ((off >> 3) & 0x70);
}

#define CP_ASYNC16(dst, src) \
    asm volatile("cp.async.cg.shared.global [%0], [%1], 16;" :: "r"(dst), "l"(src) : "memory")

#define LDSM4(r0, r1, r2, r3, addr) \
    asm volatile("ldmatrix.sync.aligned.m8n8.x4.shared.b16 {%0,%1,%2,%3}, [%4];" \
        : "=r"(r0), "=r"(r1), "=r"(r2), "=r"(r3) : "r"(addr))

__device__ __forceinline__ void mma_f16(float* d, const uint32_t* a, const uint32_t* b) {
    asm volatile(
        "mma.sync.aligned.m16n8k16.row.col.f32.f16.f16.f32 "
        "{%0,%1,%2,%3}, {%4,%5,%6,%7}, {%8,%9}, {%0,%1,%2,%3};"
        : "+f"(d[0]), "+f"(d[1]), "+f"(d[2]), "+f"(d[3])
        : "r"(a[0]), "r"(a[1]), "r"(a[2]), "r"(a[3]), "r"(b[0]), "r"(b[1]));
}

__device__ __forceinline__ unsigned int float_orderable(float f) {
    unsigned int b = __float_as_uint(f);
    return (b & 0x80000000u) ? ~b : (b | 0x80000000u);
}
__device__ __forceinline__ float orderable_to_float(unsigned int u) {
    return (u & 0x80000000u) ? __uint_as_float(u ^ 0x80000000u) : __uint_as_float(~u);
}

// ---------------------------------------------------------------------------
// fused fp32 -> fp16 conversion (A unscaled, B scaled by BSCALE), 2x unrolled
// ---------------------------------------------------------------------------
#define A8 (NROWS * DDIM / 8)
#define B8 (KCOLS * DDIM / 8)
__global__ __launch_bounds__(256)
void convert_kernel(const float* __restrict__ srcA, const float* __restrict__ srcB) {
    const int stride = gridDim.x * blockDim.x;
    for (int i = blockIdx.x * blockDim.x + threadIdx.x; i < A8 + B8; i += 2 * stride) {
#pragma unroll
        for (int u = 0; u < 2; u++) {
            int idx = i + u * stride;
            if (idx >= A8 + B8) break;
            const float4* s4;
            uint4* d4;
            float sc;
            if (idx < A8) {
                s4 = reinterpret_cast<const float4*>(srcA) + (size_t)idx * 2;
                d4 = reinterpret_cast<uint4*>(g_A16) + idx;
                sc = 1.0f;
            } else {
                s4 = reinterpret_cast<const float4*>(srcB) + (size_t)(idx - A8) * 2;
                d4 = reinterpret_cast<uint4*>(g_B16) + (idx - A8);
                sc = BSCALE;
            }
            float4 v0 = s4[0], v1 = s4[1];
            __half2 h[4];
            h[0] = __floats2half2_rn(v0.x * sc, v0.y * sc);
            h[1] = __floats2half2_rn(v0.z * sc, v0.w * sc);
            h[2] = __floats2half2_rn(v1.x * sc, v1.y * sc);
            h[3] = __floats2half2_rn(v1.z * sc, v1.w * sc);
            *d4 = *reinterpret_cast<uint4*>(h);
        }
    }
}

// ---------------------------------------------------------------------------
// fp16 tensor-core GEMM: C[NROWS, KCOLS] = A[NROWS, DDIM] * B[KCOLS, DDIM]^T
// CTA 128x128, 4 warps as 2(M) x 2(N), warp tile 64x64, fp32 accum.
// 3-stage cp.async pipeline, A-fragment double buffering, 2 CTAs/SM.
// ---------------------------------------------------------------------------
__global__ __launch_bounds__(NTHREADS, 2)
void gemm_tc_kernel(float* __restrict__ C)
{
    extern __shared__ char smem[];
    __shared__ unsigned int sMax[BM];
    const uint32_t smem_base = smem_u32(smem);
    const int tid = threadIdx.x;
    const int lane = tid & 31;
    const int wid = tid >> 5;
    const int wy = wid >> 1;     // 0..1 : M offset wy*64
    const int wx = wid & 1;      // 0..1 : N offset wx*64
    const int bx = blockIdx.x;   // N tile
    const int by = blockIdx.y;   // M tile

    sMax[tid] = 0u;

    const __half* Ab = g_A16 + (size_t)by * BM * DDIM;
    const __half* Bb = g_B16 + (size_t)bx * BN * DDIM;

    const int lrow = tid >> 3;        // 0..15
    const int lc16 = (tid & 7) * 16;  // byte col within 128B row

    float acc[4][8][4];
#pragma unroll
    for (int i = 0; i < 4; i++)
#pragma unroll
        for (int j = 0; j < 8; j++)
#pragma unroll
            for (int q = 0; q < 4; q++) acc[i][j][q] = 0.0f;

    const int rl  = lane & 7;
    const int sel = lane >> 3;
    const int a_row_off = (sel & 1) * 8 + rl;
    const int a_colb    = (sel >> 1) * 16;
    const int b_row_off = (sel >> 1) * 8 + rl;
    const int b_colb    = (sel & 1) * 16;

    auto load_tile = [&](int t) {
        const int s = t % NSTAGES;
        const uint32_t sa = smem_base + s * STAGE_BYTES;
        const uint32_t sb = sa + A_BYTES;
        const int d0 = t * BK;
#pragma unroll
        for (int k = 0; k < 8; k++) {
            int r = lrow + k * 16;
            uint32_t off = swz((uint32_t)(r * 128 + lc16));
            CP_ASYNC16(sa + off, Ab + (size_t)r * DDIM + d0 + (lc16 >> 1));
            CP_ASYNC16(sb + off, Bb + (size_t)r * DDIM + d0 + (lc16 >> 1));
        }
        asm volatile("cp.async.commit_group;" ::: "memory");
    };

    load_tile(0);
    load_tile(1);

    for (int t = 0; t < NTILES; t++) {
        if (t < NTILES - 1) asm volatile("cp.async.wait_group 1;" ::: "memory");
        else                asm volatile("cp.async.wait_group 0;" ::: "memory");
        __syncthreads();   // also orders compute(t-1) before load_tile(t+2) below
        if (t + 2 < NTILES) load_tile(t + 2);

        const int s = t % NSTAGES;
        const uint32_t sa = smem_base + s * STAGE_BYTES;
        const uint32_t sb = sa + A_BYTES;

        // A fragments double-buffered: LDSM(ks+1) issues under HMMA(ks)
        uint32_t af[2][4][4];
#pragma unroll
        for (int mt = 0; mt < 4; mt++) {
            uint32_t off = (uint32_t)((wy * 64 + mt * 16 + a_row_off) * 128 + a_colb);
            LDSM4(af[0][mt][0], af[0][mt][1], af[0][mt][2], af[0][mt][3], sa + swz(off));
        }

#pragma unroll
        for (int ks = 0; ks < 4; ks++) {        // k step = 16 fp16 = 32B
            const int k0b = ks * 32;
            uint32_t bf[8][2];
#pragma unroll
            for (int p = 0; p < 4; p++) {
                uint32_t off = (uint32_t)((wx * 64 + p * 16 + b_row_off) * 128 +
                                          k0b + b_colb);
                uint32_t r0, r1, r2, r3;
                LDSM4(r0, r1, r2, r3, sb + swz(off));
                bf[p * 2][0] = r0;     bf[p * 2][1] = r1;
                bf[p * 2 + 1][0] = r2; bf[p * 2 + 1][1] = r3;
            }
            if (ks < 3) {
#pragma unroll
                for (int mt = 0; mt < 4; mt++) {
                    uint32_t off = (uint32_t)((wy * 64 + mt * 16 + a_row_off) * 128 +
                                              (ks + 1) * 32 + a_colb);
                    LDSM4(af[(ks + 1) & 1][mt][0], af[(ks + 1) & 1][mt][1],
                          af[(ks + 1) & 1][mt][2], af[(ks + 1) & 1][mt][3],
                          sa + swz(off));
                }
            }
#pragma unroll
            for (int mt = 0; mt < 4; mt++)
#pragma unroll
                for (int nt = 0; nt < 8; nt++)
                    mma_f16(acc[mt][nt], af[ks & 1][mt], bf[nt]);
        }
        // no bottom barrier: next iteration's __syncthreads provides the ordering
    }

    // ---- epilogue: unscale, write logits + per-row tile max ----
    const int row_base = by * BM + wy * 64 + (lane >> 2);
    const int col_base = bx * BN + wx * 64 + (lane & 3) * 2;
#pragma unroll
    for (int mt = 0; mt < 4; mt++) {
        int r0 = row_base + mt * 16;
        float* C0 = C + (size_t)r0 * KCOLS + col_base;
        float* C1 = C + (size_t)(r0 + 8) * KCOLS + col_base;
        float mx0 = -3.4e38f, mx1 = -3.4e38f;
#pragma unroll
        for (int nt = 0; nt < 8; nt++) {
            float v0 = acc[mt][nt][0] * BSCALE_INV;
            float v1 = acc[mt][nt][1] * BSCALE_INV;
            float v2 = acc[mt][nt][2] * BSCALE_INV;
            float v3 = acc[mt][nt][3] * BSCALE_INV;
            *reinterpret_cast<float2*>(C0 + nt * 8) = make_float2(v0, v1);
            *reinterpret_cast<float2*>(C1 + nt * 8) = make_float2(v2, v3);
            mx0 = fmaxf(mx0, fmaxf(v0, v1));
            mx1 = fmaxf(mx1, fmaxf(v2, v3));
        }
        mx0 = fmaxf(mx0, __shfl_xor_sync(0xffffffffu, mx0, 1));
        mx0 = fmaxf(mx0, __shfl_xor_sync(0xffffffffu, mx0, 2));
        mx1 = fmaxf(mx1, __shfl_xor_sync(0xffffffffu, mx1, 1));
        mx1 = fmaxf(mx1, __shfl_xor_sync(0xffffffffu, mx1, 2));
        if ((lane & 3) == 0) {
            int rl0 = wy * 64 + mt * 16 + (lane >> 2);
            atomicMax(&sMax[rl0],     float_orderable(mx0));
            atomicMax(&sMax[rl0 + 8], float_orderable(mx1));
        }
    }
    __syncthreads();
    g_tilemax[(size_t)(by * BM + tid) * NXTILES + bx] = sMax[tid];
}

// ---------------------------------------------------------------------------
// Exact argmax from tile maxima: select near-max tiles, load only those
// logits, recompute candidates exactly in fp32. One warp per row.
// ---------------------------------------------------------------------------
__global__ __launch_bounds__(256)
void argmax_kernel(const float* __restrict__ A, const float* __restrict__ B,
                   const float* __restrict__ C, float* __restrict__ out_idx)
{
    const int n = (blockIdx.x * blockDim.x + threadIdx.x) >> 5;   // row per warp
    const int lane = threadIdx.x & 31;
    if (n >= NROWS) return;

    // hoist the A-row fragment loads: latency overlaps the scan phases below
    const float4* z4p = reinterpret_cast<const float4*>(A + (size_t)n * DDIM) + lane * 4;
    float4 za[4];
#pragma unroll
    for (int q = 0; q < 4; q++) za[q] = z4p[q];

    // lane t holds tile t's max (NXTILES == 32)
    const unsigned int tm = g_tilemax[(size_t)n * NXTILES + lane];
    unsigned int gm = tm;
#pragma unroll
    for (int off = 16; off; off >>= 1)
        gm = max(gm, __shfl_xor_sync(0xffffffffu, gm, off));

    const float fmx = orderable_to_float(gm);
    const float thr = fmx - 5e-4f;                 // >> 8x worst-case fp16 error
    const unsigned int thr_ord = float_orderable(thr);

    unsigned int tilemask = __ballot_sync(0xffffffffu, tm >= thr_ord);

    const float4* Crow = reinterpret_cast<const float4*>(C + (size_t)n * KCOLS);
    int cand[8];
    int nc = 0;
    while (tilemask) {
        int tile = __ffs(tilemask) - 1;
        tilemask &= tilemask - 1;
        float4 v = Crow[tile * 32 + lane];
        int c0 = tile * BN + lane * 4;
        if (v.x >= thr && nc < 8) cand[nc++] = c0;
        if (v.y >= thr && nc < 8) cand[nc++] = c0 + 1;
        if (v.z >= thr && nc < 8) cand[nc++] = c0 + 2;
        if (v.w >= thr && nc < 8) cand[nc++] = c0 + 3;
    }

    // exact fp32 recompute of all candidates (warp-cooperative dots)
    unsigned long long best = 0ULL;

    for (int l = 0; l < 32; l++) {
        int cnt = __shfl_sync(0xffffffffu, nc, l);
        for (int j = 0; j < cnt; j++) {
            int mycol = (j < 8) ? cand[j] : 0;
            int col = __shfl_sync(0xffffffffu, mycol, l);
            const float4* c4 = reinterpret_cast<const float4*>(B + (size_t)col * DDIM) + lane * 4;
            float sum = 0.0f;
#pragma unroll
            for (int q = 0; q < 4; q++) {
                float4 a = za[q], b = c4[q];
                sum = fmaf(a.x, b.x, sum);
                sum = fmaf(a.y, b.y, sum);
                sum = fmaf(a.z, b.z, sum);
                sum = fmaf(a.w, b.w, sum);
            }
#pragma unroll
            for (int off = 16; off; off >>= 1)
                sum += __shfl_xor_sync(0xffffffffu, sum, off);
            unsigned long long p = ((unsigned long long)float_orderable(sum) << 32) |
                                   (unsigned int)(KCOLS - 1 - col);   // lower col wins ties
            if (p > best) best = p;
        }
    }
    if (lane == 0)
        out_idx[n] = (float)(KCOLS - 1 - (unsigned int)(best & 0xFFFFFFFFu));
}

extern "C" void kernel_launch(void* const* d_in, const int* in_sizes, int n_in,
                              void* d_out, int out_size) {
    const float* z_e_x    = (const float*)d_in[0];  // [NROWS, DDIM]
    const float* codebook = (const float*)d_in[1];  // [KCOLS, DDIM]
    float* out = (float*)d_out;                      // logits then indices

    cudaFuncSetAttribute(gemm_tc_kernel, cudaFuncAttributeMaxDynamicSharedMemorySize, SMEM_TOTAL);

    convert_kernel<<<1184, 256>>>(z_e_x, codebook);   // 148 SMs * 8 blocks

    dim3 grid(KCOLS / BN, NROWS / BM);   // (32, 256), x fastest -> A-tile L2 reuse
    gemm_tc_kernel<<<grid, NTHREADS, SMEM_TOTAL>>>(out);

    long long logits_elems = (long long)NROWS * KCOLS;
    if ((long long)out_size >= logits_elems + NROWS) {
        argmax_kernel<<<NROWS / 8, 256>>>(z_e_x, codebook, out, out + logits_elems);
    }
}

// round 13
// speedup vs baseline: 1.0560x; 1.0198x over previous
#include <cuda_runtime.h>
#include <cuda_fp16.h>
#include <stdint.h>

#define NROWS 32768   // M
#define KCOLS 4096    // GEMM N (codebook entries)
#define DDIM  512     // reduction K

#define BM 128
#define BN 128
#define BK 64                    // 64 fp16 = 128B rows (SW128-native)
#define NTILES (DDIM / BK)       // 8
#define NXTILES (KCOLS / BN)     // 32
#define NTHREADS 128             // 4 warps: 2(M) x 2(N), warp tile 64x64
#define NSTAGES 3

#define BSCALE 4096.0f           // 2^12: lifts codebook out of fp16 subnormals
#define BSCALE_INV (1.0f / 4096.0f)

#define A_BYTES (BM * BK * 2)               // 16384
#define B_BYTES (BN * BK * 2)               // 16384
#define STAGE_BYTES (A_BYTES + B_BYTES)     // 32768
#define SMEM_TOTAL (NSTAGES * STAGE_BYTES)  // 98304; occ 2 -> 192KB <= 228KB

// fp16 copies of the operands (written by convert kernel each launch)
__device__ __half g_A16[NROWS * DDIM];   // 32 MB
__device__ __half g_B16[KCOLS * DDIM];   // 4 MB (scaled by BSCALE)

// per-(row, N-tile) max of fp16-path logits, orderable uint. 4MB. Fully
// rewritten by the GEMM epilogue every launch -> no init needed.
__device__ unsigned int g_tilemax[NROWS * NXTILES];

__device__ __forceinline__ uint32_t smem_u32(const void* p) {
    uint32_t a;
    asm("{ .reg .u64 t; cvta.to.shared.u64 t, %1; cvt.u32.u64 %0, t; }" : "=r"(a) : "l"(p));
    return a;
}
__device__ __forceinline__ uint32_t swz(uint32_t off) {   // SW128
    return off ^ ((off >> 3) & 0x70);
}

#define CP_ASYNC16(dst, src) \
    asm volatile("cp.async.cg.shared.global [%0], [%1], 16;" :: "r"(dst), "l"(src) : "memory")

#define LDSM4(r0, r1, r2, r3, addr) \
    asm volatile("ldmatrix.sync.aligned.m8n8.x4.shared.b16 {%0,%1,%2,%3}, [%4];" \
        : "=r"(r0), "=r"(r1), "=r"(r2), "=r"(r3) : "r"(addr))

__device__ __forceinline__ void mma_f16(float* d, const uint32_t* a, const uint32_t* b) {
    asm volatile(
        "mma.sync.aligned.m16n8k16.row.col.f32.f16.f16.f32 "
        "{%0,%1,%2,%3}, {%4,%5,%6,%7}, {%8,%9}, {%0,%1,%2,%3};"
        : "+f"(d[0]), "+f"(d[1]), "+f"(d[2]), "+f"(d[3])
        : "r"(a[0]), "r"(a[1]), "r"(a[2]), "r"(a[3]), "r"(b[0]), "r"(b[1]));
}

__device__ __forceinline__ unsigned int float_orderable(float f) {
    unsigned int b = __float_as_uint(f);
    return (b & 0x80000000u) ? ~b : (b | 0x80000000u);
}
__device__ __forceinline__ float orderable_to_float(unsigned int u) {
    return (u & 0x80000000u) ? __uint_as_float(u ^ 0x80000000u) : __uint_as_float(~u);
}

// ---------------------------------------------------------------------------
// fused fp32 -> fp16 conversion (A unscaled, B scaled by BSCALE), 2x unrolled
// ---------------------------------------------------------------------------
#define A8 (NROWS * DDIM / 8)
#define B8 (KCOLS * DDIM / 8)
__global__ __launch_bounds__(256)
void convert_kernel(const float* __restrict__ srcA, const float* __restrict__ srcB) {
    const int stride = gridDim.x * blockDim.x;
    for (int i = blockIdx.x * blockDim.x + threadIdx.x; i < A8 + B8; i += 2 * stride) {
#pragma unroll
        for (int u = 0; u < 2; u++) {
            int idx = i + u * stride;
            if (idx >= A8 + B8) break;
            const float4* s4;
            uint4* d4;
            float sc;
            if (idx < A8) {
                s4 = reinterpret_cast<const float4*>(srcA) + (size_t)idx * 2;
                d4 = reinterpret_cast<uint4*>(g_A16) + idx;
                sc = 1.0f;
            } else {
                s4 = reinterpret_cast<const float4*>(srcB) + (size_t)(idx - A8) * 2;
                d4 = reinterpret_cast<uint4*>(g_B16) + (idx - A8);
                sc = BSCALE;
            }
            float4 v0 = s4[0], v1 = s4[1];
            __half2 h[4];
            h[0] = __floats2half2_rn(v0.x * sc, v0.y * sc);
            h[1] = __floats2half2_rn(v0.z * sc, v0.w * sc);
            h[2] = __floats2half2_rn(v1.x * sc, v1.y * sc);
            h[3] = __floats2half2_rn(v1.z * sc, v1.w * sc);
            *d4 = *reinterpret_cast<uint4*>(h);
        }
    }
}

// ---------------------------------------------------------------------------
// fp16 tensor-core GEMM: C[NROWS, KCOLS] = A[NROWS, DDIM] * B[KCOLS, DDIM]^T
// CTA 128x128, 4 warps as 2(M) x 2(N), warp tile 64x64, fp32 accum.
// 3-stage cp.async pipeline, A-fragment double buffering, 2 CTAs/SM.
// ---------------------------------------------------------------------------
__global__ __launch_bounds__(NTHREADS, 2)
void gemm_tc_kernel(float* __restrict__ C)
{
    extern __shared__ char smem[];
    __shared__ unsigned int sMax[BM];
    const uint32_t smem_base = smem_u32(smem);
    const int tid = threadIdx.x;
    const int lane = tid & 31;
    const int wid = tid >> 5;
    const int wy = wid >> 1;     // 0..1 : M offset wy*64
    const int wx = wid & 1;      // 0..1 : N offset wx*64
    const int bx = blockIdx.x;   // N tile
    const int by = blockIdx.y;   // M tile

    sMax[tid] = 0u;

    const __half* Ab = g_A16 + (size_t)by * BM * DDIM;
    const __half* Bb = g_B16 + (size_t)bx * BN * DDIM;

    const int lrow = tid >> 3;        // 0..15
    const int lc16 = (tid & 7) * 16;  // byte col within 128B row

    float acc[4][8][4];
#pragma unroll
    for (int i = 0; i < 4; i++)
#pragma unroll
        for (int j = 0; j < 8; j++)
#pragma unroll
            for (int q = 0; q < 4; q++) acc[i][j][q] = 0.0f;

    const int rl  = lane & 7;
    const int sel = lane >> 3;
    const int a_row_off = (sel & 1) * 8 + rl;
    const int a_colb    = (sel >> 1) * 16;
    const int b_row_off = (sel >> 1) * 8 + rl;
    const int b_colb    = (sel & 1) * 16;

    auto load_tile = [&](int t) {
        const int s = t % NSTAGES;
        const uint32_t sa = smem_base + s * STAGE_BYTES;
        const uint32_t sb = sa + A_BYTES;
        const int d0 = t * BK;
#pragma unroll
        for (int k = 0; k < 8; k++) {
            int r = lrow + k * 16;
            uint32_t off = swz((uint32_t)(r * 128 + lc16));
            CP_ASYNC16(sa + off, Ab + (size_t)r * DDIM + d0 + (lc16 >> 1));
            CP_ASYNC16(sb + off, Bb + (size_t)r * DDIM + d0 + (lc16 >> 1));
        }
        asm volatile("cp.async.commit_group;" ::: "memory");
    };

    load_tile(0);
    load_tile(1);

    for (int t = 0; t < NTILES; t++) {
        if (t < NTILES - 1) asm volatile("cp.async.wait_group 1;" ::: "memory");
        else                asm volatile("cp.async.wait_group 0;" ::: "memory");
        __syncthreads();   // also orders compute(t-1) before load_tile(t+2) below
        if (t + 2 < NTILES) load_tile(t + 2);

        const int s = t % NSTAGES;
        const uint32_t sa = smem_base + s * STAGE_BYTES;
        const uint32_t sb = sa + A_BYTES;

        // A fragments double-buffered: LDSM(ks+1) issues under HMMA(ks)
        uint32_t af[2][4][4];
#pragma unroll
        for (int mt = 0; mt < 4; mt++) {
            uint32_t off = (uint32_t)((wy * 64 + mt * 16 + a_row_off) * 128 + a_colb);
            LDSM4(af[0][mt][0], af[0][mt][1], af[0][mt][2], af[0][mt][3], sa + swz(off));
        }

#pragma unroll
        for (int ks = 0; ks < 4; ks++) {        // k step = 16 fp16 = 32B
            const int k0b = ks * 32;
            uint32_t bf[8][2];
#pragma unroll
            for (int p = 0; p < 4; p++) {
                uint32_t off = (uint32_t)((wx * 64 + p * 16 + b_row_off) * 128 +
                                          k0b + b_colb);
                uint32_t r0, r1, r2, r3;
                LDSM4(r0, r1, r2, r3, sb + swz(off));
                bf[p * 2][0] = r0;     bf[p * 2][1] = r1;
                bf[p * 2 + 1][0] = r2; bf[p * 2 + 1][1] = r3;
            }
            if (ks < 3) {
#pragma unroll
                for (int mt = 0; mt < 4; mt++) {
                    uint32_t off = (uint32_t)((wy * 64 + mt * 16 + a_row_off) * 128 +
                                              (ks + 1) * 32 + a_colb);
                    LDSM4(af[(ks + 1) & 1][mt][0], af[(ks + 1) & 1][mt][1],
                          af[(ks + 1) & 1][mt][2], af[(ks + 1) & 1][mt][3],
                          sa + swz(off));
                }
            }
#pragma unroll
            for (int mt = 0; mt < 4; mt++)
#pragma unroll
                for (int nt = 0; nt < 8; nt++)
                    mma_f16(acc[mt][nt], af[ks & 1][mt], bf[nt]);
        }
        // no bottom barrier: next iteration's __syncthreads provides the ordering
    }

    // ---- epilogue: unscale, write logits + per-row tile max ----
    const int row_base = by * BM + wy * 64 + (lane >> 2);
    const int col_base = bx * BN + wx * 64 + (lane & 3) * 2;
#pragma unroll
    for (int mt = 0; mt < 4; mt++) {
        int r0 = row_base + mt * 16;
        float* C0 = C + (size_t)r0 * KCOLS + col_base;
        float* C1 = C + (size_t)(r0 + 8) * KCOLS + col_base;
        float mx0 = -3.4e38f, mx1 = -3.4e38f;
#pragma unroll
        for (int nt = 0; nt < 8; nt++) {
            float v0 = acc[mt][nt][0] * BSCALE_INV;
            float v1 = acc[mt][nt][1] * BSCALE_INV;
            float v2 = acc[mt][nt][2] * BSCALE_INV;
            float v3 = acc[mt][nt][3] * BSCALE_INV;
            *reinterpret_cast<float2*>(C0 + nt * 8) = make_float2(v0, v1);
            *reinterpret_cast<float2*>(C1 + nt * 8) = make_float2(v2, v3);
            mx0 = fmaxf(mx0, fmaxf(v0, v1));
            mx1 = fmaxf(mx1, fmaxf(v2, v3));
        }
        mx0 = fmaxf(mx0, __shfl_xor_sync(0xffffffffu, mx0, 1));
        mx0 = fmaxf(mx0, __shfl_xor_sync(0xffffffffu, mx0, 2));
        mx1 = fmaxf(mx1, __shfl_xor_sync(0xffffffffu, mx1, 1));
        mx1 = fmaxf(mx1, __shfl_xor_sync(0xffffffffu, mx1, 2));
        if ((lane & 3) == 0) {
            int rl0 = wy * 64 + mt * 16 + (lane >> 2);
            atomicMax(&sMax[rl0],     float_orderable(mx0));
            atomicMax(&sMax[rl0 + 8], float_orderable(mx1));
        }
    }
    __syncthreads();
    g_tilemax[(size_t)(by * BM + tid) * NXTILES + bx] = sMax[tid];
}

// ---------------------------------------------------------------------------
// Exact argmax from tile maxima: select near-max tiles, load only those
// logits, warp-compact the candidates, recompute them exactly in fp32.
// One warp per row.
// ---------------------------------------------------------------------------
__global__ __launch_bounds__(256)
void argmax_kernel(const float* __restrict__ A, const float* __restrict__ B,
                   const float* __restrict__ C, float* __restrict__ out_idx)
{
    __shared__ int sCand[8][20];          // per-warp compacted candidate list
    const int warp_in_blk = threadIdx.x >> 5;
    const int n = (blockIdx.x * blockDim.x + threadIdx.x) >> 5;   // row per warp
    const int lane = threadIdx.x & 31;
    if (n >= NROWS) return;

    // hoist the A-row fragment loads: latency overlaps the scan phases below
    const float4* z4p = reinterpret_cast<const float4*>(A + (size_t)n * DDIM) + lane * 4;
    float4 za[4];
#pragma unroll
    for (int q = 0; q < 4; q++) za[q] = z4p[q];

    // lane t holds tile t's max (NXTILES == 32)
    const unsigned int tm = g_tilemax[(size_t)n * NXTILES + lane];
    unsigned int gm = tm;
#pragma unroll
    for (int off = 16; off; off >>= 1)
        gm = max(gm, __shfl_xor_sync(0xffffffffu, gm, off));

    const float fmx = orderable_to_float(gm);
    const float thr = fmx - 5e-4f;                 // >> 8x worst-case fp16 error
    const unsigned int thr_ord = float_orderable(thr);

    unsigned int tilemask = __ballot_sync(0xffffffffu, tm >= thr_ord);

    const float4* Crow = reinterpret_cast<const float4*>(C + (size_t)n * KCOLS);
    int cand[4];
    int nc = 0;
    while (tilemask) {
        int tile = __ffs(tilemask) - 1;
        tilemask &= tilemask - 1;
        float4 v = Crow[tile * 32 + lane];
        int c0 = tile * BN + lane * 4;
        if (v.x >= thr && nc < 4) cand[nc++] = c0;
        if (v.y >= thr && nc < 4) cand[nc++] = c0 + 1;
        if (v.z >= thr && nc < 4) cand[nc++] = c0 + 2;
        if (v.w >= thr && nc < 4) cand[nc++] = c0 + 3;
    }

    // warp-compact candidates into smem via exclusive prefix over lane counts
    int pfx = nc;
#pragma unroll
    for (int off = 1; off < 32; off <<= 1) {
        int v = __shfl_up_sync(0xffffffffu, pfx, off);
        if (lane >= off) pfx += v;
    }
    int total = __shfl_sync(0xffffffffu, pfx, 31);
    int base = pfx - nc;
    if (total > 20) total = 20;
    for (int j = 0; j < nc; j++) {
        int pos = base + j;
        if (pos < 20) sCand[warp_in_blk][pos] = cand[j];
    }
    __syncwarp();

    // exact fp32 recompute of the (typically 1) compacted candidates
    unsigned long long best = 0ULL;
    for (int e = 0; e < total; e++) {
        int col = sCand[warp_in_blk][e];
        const float4* c4 = reinterpret_cast<const float4*>(B + (size_t)col * DDIM) + lane * 4;
        float sum = 0.0f;
#pragma unroll
        for (int q = 0; q < 4; q++) {
            float4 a = za[q], b = c4[q];
            sum = fmaf(a.x, b.x, sum);
            sum = fmaf(a.y, b.y, sum);
            sum = fmaf(a.z, b.z, sum);
            sum = fmaf(a.w, b.w, sum);
        }
#pragma unroll
        for (int off = 16; off; off >>= 1)
            sum += __shfl_xor_sync(0xffffffffu, sum, off);
        unsigned long long p = ((unsigned long long)float_orderable(sum) << 32) |
                               (unsigned int)(KCOLS - 1 - col);   // lower col wins ties
        if (p > best) best = p;
    }
    if (lane == 0)
        out_idx[n] = (float)(KCOLS - 1 - (unsigned int)(best & 0xFFFFFFFFu));
}

extern "C" void kernel_launch(void* const* d_in, const int* in_sizes, int n_in,
                              void* d_out, int out_size) {
    const float* z_e_x    = (const float*)d_in[0];  // [NROWS, DDIM]
    const float* codebook = (const float*)d_in[1];  // [KCOLS, DDIM]
    float* out = (float*)d_out;                      // logits then indices

    cudaFuncSetAttribute(gemm_tc_kernel, cudaFuncAttributeMaxDynamicSharedMemorySize, SMEM_TOTAL);

    convert_kernel<<<1184, 256>>>(z_e_x, codebook);   // 148 SMs * 8 blocks

    dim3 grid(KCOLS / BN, NROWS / BM);   // (32, 256), x fastest -> A-tile L2 reuse
    gemm_tc_kernel<<<grid, NTHREADS, SMEM_TOTAL>>>(out);

    long long logits_elems = (long long)NROWS * KCOLS;
    if ((long long)out_size >= logits_elems + NROWS) {
        argmax_kernel<<<NROWS / 8, 256>>>(z_e_x, codebook, out, out + logits_elems);
    }
}

// round 14
// speedup vs baseline: 1.0621x; 1.0058x over previous
#include <cuda_runtime.h>
#include <cuda_fp16.h>
#include <stdint.h>

#define NROWS 32768   // M
#define KCOLS 4096    // GEMM N (codebook entries)
#define DDIM  512     // reduction K

#define BM 128
#define BN 128
#define BK 64                    // 64 fp16 = 128B rows (SW128-native)
#define NTILES (DDIM / BK)       // 8
#define NXTILES (KCOLS / BN)     // 32
#define NTHREADS 128             // 4 warps: 2(M) x 2(N), warp tile 64x64
#define NSTAGES 3

#define BSCALE 4096.0f           // 2^12: lifts codebook out of fp16 subnormals
#define BSCALE_INV (1.0f / 4096.0f)

#define A_BYTES (BM * BK * 2)               // 16384
#define B_BYTES (BN * BK * 2)               // 16384
#define STAGE_BYTES (A_BYTES + B_BYTES)     // 32768
#define SMEM_TOTAL (NSTAGES * STAGE_BYTES)  // 98304; occ 2 -> 192KB <= 228KB

// fp16 copies of the operands (written by convert kernel each launch)
__device__ __half g_A16[NROWS * DDIM];   // 32 MB
__device__ __half g_B16[KCOLS * DDIM];   // 4 MB (scaled by BSCALE)

// per-(row, N-tile) max of fp16-path logits, orderable uint. 4MB. Fully
// rewritten by the GEMM epilogue every launch -> no init needed.
__device__ unsigned int g_tilemax[NROWS * NXTILES];

__device__ __forceinline__ uint32_t smem_u32(const void* p) {
    uint32_t a;
    asm("{ .reg .u64 t; cvta.to.shared.u64 t, %1; cvt.u32.u64 %0, t; }" : "=r"(a) : "l"(p));
    return a;
}
__device__ __forceinline__ uint32_t swz(uint32_t off) {   // SW128
    return off ^ ((off >> 3) & 0x70);
}

#define CP_ASYNC16(dst, src) \
    asm volatile("cp.async.cg.shared.global [%0], [%1], 16;" :: "r"(dst), "l"(src) : "memory")

#define LDSM4(r0, r1, r2, r3, addr) \
    asm volatile("ldmatrix.sync.aligned.m8n8.x4.shared.b16 {%0,%1,%2,%3}, [%4];" \
        : "=r"(r0), "=r"(r1), "=r"(r2), "=r"(r3) : "r"(addr))

__device__ __forceinline__ void mma_f16(float* d, const uint32_t* a, const uint32_t* b) {
    asm volatile(
        "mma.sync.aligned.m16n8k16.row.col.f32.f16.f16.f32 "
        "{%0,%1,%2,%3}, {%4,%5,%6,%7}, {%8,%9}, {%0,%1,%2,%3};"
        : "+f"(d[0]), "+f"(d[1]), "+f"(d[2]), "+f"(d[3])
        : "r"(a[0]), "r"(a[1]), "r"(a[2]), "r"(a[3]), "r"(b[0]), "r"(b[1]));
}

__device__ __forceinline__ unsigned int float_orderable(float f) {
    unsigned int b = __float_as_uint(f);
    return (b & 0x80000000u) ? ~b : (b | 0x80000000u);
}
__device__ __forceinline__ float orderable_to_float(unsigned int u) {
    return (u & 0x80000000u) ? __uint_as_float(u ^ 0x80000000u) : __uint_as_float(~u);
}

// ---------------------------------------------------------------------------
// fused fp32 -> fp16 conversion (A unscaled, B scaled by BSCALE), 2x unrolled
// ---------------------------------------------------------------------------
#define A8 (NROWS * DDIM / 8)
#define B8 (KCOLS * DDIM / 8)
__global__ __launch_bounds__(256)
void convert_kernel(const float* __restrict__ srcA, const float* __restrict__ srcB) {
    const int stride = gridDim.x * blockDim.x;
    for (int i = blockIdx.x * blockDim.x + threadIdx.x; i < A8 + B8; i += 2 * stride) {
#pragma unroll
        for (int u = 0; u < 2; u++) {
            int idx = i + u * stride;
            if (idx >= A8 + B8) break;
            const float4* s4;
            uint4* d4;
            float sc;
            if (idx < A8) {
                s4 = reinterpret_cast<const float4*>(srcA) + (size_t)idx * 2;
                d4 = reinterpret_cast<uint4*>(g_A16) + idx;
                sc = 1.0f;
            } else {
                s4 = reinterpret_cast<const float4*>(srcB) + (size_t)(idx - A8) * 2;
                d4 = reinterpret_cast<uint4*>(g_B16) + (idx - A8);
                sc = BSCALE;
            }
            float4 v0 = s4[0], v1 = s4[1];
            __half2 h[4];
            h[0] = __floats2half2_rn(v0.x * sc, v0.y * sc);
            h[1] = __floats2half2_rn(v0.z * sc, v0.w * sc);
            h[2] = __floats2half2_rn(v1.x * sc, v1.y * sc);
            h[3] = __floats2half2_rn(v1.z * sc, v1.w * sc);
            *d4 = *reinterpret_cast<uint4*>(h);
        }
    }
}

// ---------------------------------------------------------------------------
// fp16 tensor-core GEMM: C[NROWS, KCOLS] = A[NROWS, DDIM] * B[KCOLS, DDIM]^T
// CTA 128x128, 4 warps as 2(M) x 2(N), warp tile 64x64, fp32 accum.
// 3-stage cp.async pipeline, A-fragment double buffering, 2 CTAs/SM.
// ---------------------------------------------------------------------------
__global__ __launch_bounds__(NTHREADS, 2)
void gemm_tc_kernel(float* __restrict__ C)
{
    extern __shared__ char smem[];
    __shared__ unsigned int sMax[BM];
    const uint32_t smem_base = smem_u32(smem);
    const int tid = threadIdx.x;
    const int lane = tid & 31;
    const int wid = tid >> 5;
    const int wy = wid >> 1;     // 0..1 : M offset wy*64
    const int wx = wid & 1;      // 0..1 : N offset wx*64
    const int bx = blockIdx.x;   // N tile
    const int by = blockIdx.y;   // M tile

    sMax[tid] = 0u;

    const __half* Ab = g_A16 + (size_t)by * BM * DDIM;
    const __half* Bb = g_B16 + (size_t)bx * BN * DDIM;

    const int lrow = tid >> 3;        // 0..15
    const int lc16 = (tid & 7) * 16;  // byte col within 128B row

    float acc[4][8][4];
#pragma unroll
    for (int i = 0; i < 4; i++)
#pragma unroll
        for (int j = 0; j < 8; j++)
#pragma unroll
            for (int q = 0; q < 4; q++) acc[i][j][q] = 0.0f;

    const int rl  = lane & 7;
    const int sel = lane >> 3;
    const int a_row_off = (sel & 1) * 8 + rl;
    const int a_colb    = (sel >> 1) * 16;
    const int b_row_off = (sel >> 1) * 8 + rl;
    const int b_colb    = (sel & 1) * 16;

    auto load_tile = [&](int t) {
        const int s = t % NSTAGES;
        const uint32_t sa = smem_base + s * STAGE_BYTES;
        const uint32_t sb = sa + A_BYTES;
        const int d0 = t * BK;
#pragma unroll
        for (int k = 0; k < 8; k++) {
            int r = lrow + k * 16;
            uint32_t off = swz((uint32_t)(r * 128 + lc16));
            CP_ASYNC16(sa + off, Ab + (size_t)r * DDIM + d0 + (lc16 >> 1));
            CP_ASYNC16(sb + off, Bb + (size_t)r * DDIM + d0 + (lc16 >> 1));
        }
        asm volatile("cp.async.commit_group;" ::: "memory");
    };

    load_tile(0);
    load_tile(1);

    for (int t = 0; t < NTILES; t++) {
        if (t < NTILES - 1) asm volatile("cp.async.wait_group 1;" ::: "memory");
        else                asm volatile("cp.async.wait_group 0;" ::: "memory");
        __syncthreads();   // also orders compute(t-1) before load_tile(t+2) below
        if (t + 2 < NTILES) load_tile(t + 2);

        const int s = t % NSTAGES;
        const uint32_t sa = smem_base + s * STAGE_BYTES;
        const uint32_t sb = sa + A_BYTES;

        // A fragments double-buffered: LDSM(ks+1) issues under HMMA(ks)
        uint32_t af[2][4][4];
#pragma unroll
        for (int mt = 0; mt < 4; mt++) {
            uint32_t off = (uint32_t)((wy * 64 + mt * 16 + a_row_off) * 128 + a_colb);
            LDSM4(af[0][mt][0], af[0][mt][1], af[0][mt][2], af[0][mt][3], sa + swz(off));
        }

#pragma unroll
        for (int ks = 0; ks < 4; ks++) {        // k step = 16 fp16 = 32B
            const int k0b = ks * 32;
            uint32_t bf[8][2];
#pragma unroll
            for (int p = 0; p < 4; p++) {
                uint32_t off = (uint32_t)((wx * 64 + p * 16 + b_row_off) * 128 +
                                          k0b + b_colb);
                uint32_t r0, r1, r2, r3;
                LDSM4(r0, r1, r2, r3, sb + swz(off));
                bf[p * 2][0] = r0;     bf[p * 2][1] = r1;
                bf[p * 2 + 1][0] = r2; bf[p * 2 + 1][1] = r3;
            }
            if (ks < 3) {
#pragma unroll
                for (int mt = 0; mt < 4; mt++) {
                    uint32_t off = (uint32_t)((wy * 64 + mt * 16 + a_row_off) * 128 +
                                              (ks + 1) * 32 + a_colb);
                    LDSM4(af[(ks + 1) & 1][mt][0], af[(ks + 1) & 1][mt][1],
                          af[(ks + 1) & 1][mt][2], af[(ks + 1) & 1][mt][3],
                          sa + swz(off));
                }
            }
#pragma unroll
            for (int mt = 0; mt < 4; mt++)
#pragma unroll
                for (int nt = 0; nt < 8; nt++)
                    mma_f16(acc[mt][nt], af[ks & 1][mt], bf[nt]);
        }
        // no bottom barrier: next iteration's __syncthreads provides the ordering
    }

    // ---- epilogue: unscale, write logits + per-row tile max ----
    const int row_base = by * BM + wy * 64 + (lane >> 2);
    const int col_base = bx * BN + wx * 64 + (lane & 3) * 2;
#pragma unroll
    for (int mt = 0; mt < 4; mt++) {
        int r0 = row_base + mt * 16;
        float* C0 = C + (size_t)r0 * KCOLS + col_base;
        float* C1 = C + (size_t)(r0 + 8) * KCOLS + col_base;
        float mx0 = -3.4e38f, mx1 = -3.4e38f;
#pragma unroll
        for (int nt = 0; nt < 8; nt++) {
            float v0 = acc[mt][nt][0] * BSCALE_INV;
            float v1 = acc[mt][nt][1] * BSCALE_INV;
            float v2 = acc[mt][nt][2] * BSCALE_INV;
            float v3 = acc[mt][nt][3] * BSCALE_INV;
            *reinterpret_cast<float2*>(C0 + nt * 8) = make_float2(v0, v1);
            *reinterpret_cast<float2*>(C1 + nt * 8) = make_float2(v2, v3);
            mx0 = fmaxf(mx0, fmaxf(v0, v1));
            mx1 = fmaxf(mx1, fmaxf(v2, v3));
        }
        mx0 = fmaxf(mx0, __shfl_xor_sync(0xffffffffu, mx0, 1));
        mx0 = fmaxf(mx0, __shfl_xor_sync(0xffffffffu, mx0, 2));
        mx1 = fmaxf(mx1, __shfl_xor_sync(0xffffffffu, mx1, 1));
        mx1 = fmaxf(mx1, __shfl_xor_sync(0xffffffffu, mx1, 2));
        if ((lane & 3) == 0) {
            int rl0 = wy * 64 + mt * 16 + (lane >> 2);
            atomicMax(&sMax[rl0],     float_orderable(mx0));
            atomicMax(&sMax[rl0 + 8], float_orderable(mx1));
        }
    }
    __syncthreads();
    g_tilemax[(size_t)(by * BM + tid) * NXTILES + bx] = sMax[tid];
}

// ---------------------------------------------------------------------------
// Exact argmax from tile maxima. Fast path: if the candidate set (cols within
// a threshold band that provably contains the true fp32 argmax) is a
// singleton, that column IS the argmax -- no recompute, no A/B traffic.
// Slow path (rare): exact fp32 warp-dot over all candidates.
// ---------------------------------------------------------------------------
__global__ __launch_bounds__(256)
void argmax_kernel(const float* __restrict__ A, const float* __restrict__ B,
                   const float* __restrict__ C, float* __restrict__ out_idx)
{
    __shared__ int sCand[8][20];          // per-warp compacted candidate list
    const int warp_in_blk = threadIdx.x >> 5;
    const int n = (blockIdx.x * blockDim.x + threadIdx.x) >> 5;   // row per warp
    const int lane = threadIdx.x & 31;
    if (n >= NROWS) return;

    // lane t holds tile t's max (NXTILES == 32)
    const unsigned int tm = g_tilemax[(size_t)n * NXTILES + lane];
    unsigned int gm = tm;
#pragma unroll
    for (int off = 16; off; off >>= 1)
        gm = max(gm, __shfl_xor_sync(0xffffffffu, gm, off));

    const float fmx = orderable_to_float(gm);
    const float thr = fmx - 5e-4f;                 // >> 8x worst-case fp16 error
    const unsigned int thr_ord = float_orderable(thr);

    unsigned int tilemask = __ballot_sync(0xffffffffu, tm >= thr_ord);

    const float4* Crow = reinterpret_cast<const float4*>(C + (size_t)n * KCOLS);
    int cand[4];
    int nc = 0;
    while (tilemask) {
        int tile = __ffs(tilemask) - 1;
        tilemask &= tilemask - 1;
        float4 v = Crow[tile * 32 + lane];
        int c0 = tile * BN + lane * 4;
        if (v.x >= thr && nc < 4) cand[nc++] = c0;
        if (v.y >= thr && nc < 4) cand[nc++] = c0 + 1;
        if (v.z >= thr && nc < 4) cand[nc++] = c0 + 2;
        if (v.w >= thr && nc < 4) cand[nc++] = c0 + 3;
    }

    // warp-compact candidates via exclusive prefix over lane counts
    int pfx = nc;
#pragma unroll
    for (int off = 1; off < 32; off <<= 1) {
        int v = __shfl_up_sync(0xffffffffu, pfx, off);
        if (lane >= off) pfx += v;
    }
    int total = __shfl_sync(0xffffffffu, pfx, 31);
    int base = pfx - nc;

    // ---- fast path: singleton candidate set -> it is the argmax ----
    if (total == 1) {
        unsigned int bal = __ballot_sync(0xffffffffu, nc > 0);
        int src = __ffs(bal) - 1;
        int col = __shfl_sync(0xffffffffu, cand[0], src);
        if (lane == 0) out_idx[n] = (float)col;
        return;
    }

    if (total > 20) total = 20;
    for (int j = 0; j < nc; j++) {
        int pos = base + j;
        if (pos < 20) sCand[warp_in_blk][pos] = cand[j];
    }
    __syncwarp();

    // ---- slow path: exact fp32 recompute of all candidates ----
    const float4* z4p = reinterpret_cast<const float4*>(A + (size_t)n * DDIM) + lane * 4;
    float4 za[4];
#pragma unroll
    for (int q = 0; q < 4; q++) za[q] = z4p[q];

    unsigned long long best = 0ULL;
    for (int e = 0; e < total; e++) {
        int col = sCand[warp_in_blk][e];
        const float4* c4 = reinterpret_cast<const float4*>(B + (size_t)col * DDIM) + lane * 4;
        float sum = 0.0f;
#pragma unroll
        for (int q = 0; q < 4; q++) {
            float4 a = za[q], b = c4[q];
            sum = fmaf(a.x, b.x, sum);
            sum = fmaf(a.y, b.y, sum);
            sum = fmaf(a.z, b.z, sum);
            sum = fmaf(a.w, b.w, sum);
        }
#pragma unroll
        for (int off = 16; off; off >>= 1)
            sum += __shfl_xor_sync(0xffffffffu, sum, off);
        unsigned long long p = ((unsigned long long)float_orderable(sum) << 32) |
                               (unsigned int)(KCOLS - 1 - col);   // lower col wins ties
        if (p > best) best = p;
    }
    if (lane == 0)
        out_idx[n] = (float)(KCOLS - 1 - (unsigned int)(best & 0xFFFFFFFFu));
}

extern "C" void kernel_launch(void* const* d_in, const int* in_sizes, int n_in,
                              void* d_out, int out_size) {
    const float* z_e_x    = (const float*)d_in[0];  // [NROWS, DDIM]
    const float* codebook = (const float*)d_in[1];  // [KCOLS, DDIM]
    float* out = (float*)d_out;                      // logits then indices

    cudaFuncSetAttribute(gemm_tc_kernel, cudaFuncAttributeMaxDynamicSharedMemorySize, SMEM_TOTAL);

    convert_kernel<<<1184, 256>>>(z_e_x, codebook);   // 148 SMs * 8 blocks

    dim3 grid(KCOLS / BN, NROWS / BM);   // (32, 256), x fastest -> A-tile L2 reuse
    gemm_tc_kernel<<<grid, NTHREADS, SMEM_TOTAL>>>(out);

    long long logits_elems = (long long)NROWS * KCOLS;
    if ((long long)out_size >= logits_elems + NROWS) {
        argmax_kernel<<<NROWS / 8, 256>>>(z_e_x, codebook, out, out + logits_elems);
    }
}

// round 15
// speedup vs baseline: 1.0669x; 1.0045x over previous
#include <cuda_runtime.h>
#include <cuda_fp16.h>
#include <stdint.h>

#define NROWS 32768   // M
#define KCOLS 4096    // GEMM N (codebook entries)
#define DDIM  512     // reduction K

#define BM 128
#define BN 128
#define BK 64                    // 64 fp16 = 128B rows (SW128-native)
#define NTILES (DDIM / BK)       // 8
#define NXTILES (KCOLS / BN)     // 32
#define NTHREADS 128             // 4 warps: 2(M) x 2(N), warp tile 64x64
#define NSTAGES 2

#define BSCALE 4096.0f           // 2^12: lifts codebook out of fp16 subnormals
#define BSCALE_INV (1.0f / 4096.0f)

#define A_BYTES (BM * BK * 2)               // 16384
#define B_BYTES (BN * BK * 2)               // 16384
#define STAGE_BYTES (A_BYTES + B_BYTES)     // 32768
#define SMEM_TOTAL (NSTAGES * STAGE_BYTES)  // 65536; occ 3 -> 192KB <= 228KB

// fp16 copies of the operands (written by convert kernel each launch)
__device__ __half g_A16[NROWS * DDIM];   // 32 MB
__device__ __half g_B16[KCOLS * DDIM];   // 4 MB (scaled by BSCALE)

// per-(row, N-tile) max of fp16-path logits, orderable uint. 4MB. Fully
// rewritten by the GEMM epilogue every launch -> no init needed.
__device__ unsigned int g_tilemax[NROWS * NXTILES];

__device__ __forceinline__ uint32_t smem_u32(const void* p) {
    uint32_t a;
    asm("{ .reg .u64 t; cvta.to.shared.u64 t, %1; cvt.u32.u64 %0, t; }" : "=r"(a) : "l"(p));
    return a;
}
__device__ __forceinline__ uint32_t swz(uint32_t off) {   // SW128
    return off ^ ((off >> 3) & 0x70);
}

#define CP_ASYNC16(dst, src) \
    asm volatile("cp.async.cg.shared.global [%0], [%1], 16;" :: "r"(dst), "l"(src) : "memory")

#define LDSM4(r0, r1, r2, r3, addr) \
    asm volatile("ldmatrix.sync.aligned.m8n8.x4.shared.b16 {%0,%1,%2,%3}, [%4];" \
        : "=r"(r0), "=r"(r1), "=r"(r2), "=r"(r3) : "r"(addr))

__device__ __forceinline__ void mma_f16(float* d, const uint32_t* a, const uint32_t* b) {
    asm volatile(
        "mma.sync.aligned.m16n8k16.row.col.f32.f16.f16.f32 "
        "{%0,%1,%2,%3}, {%4,%5,%6,%7}, {%8,%9}, {%0,%1,%2,%3};"
        : "+f"(d[0]), "+f"(d[1]), "+f"(d[2]), "+f"(d[3])
        : "r"(a[0]), "r"(a[1]), "r"(a[2]), "r"(a[3]), "r"(b[0]), "r"(b[1]));
}

__device__ __forceinline__ unsigned int float_orderable(float f) {
    unsigned int b = __float_as_uint(f);
    return (b & 0x80000000u) ? ~b : (b | 0x80000000u);
}
__device__ __forceinline__ float orderable_to_float(unsigned int u) {
    return (u & 0x80000000u) ? __uint_as_float(u ^ 0x80000000u) : __uint_as_float(~u);
}

// ---------------------------------------------------------------------------
// fused fp32 -> fp16 conversion (A unscaled, B scaled by BSCALE), 2x unrolled
// ---------------------------------------------------------------------------
#define A8 (NROWS * DDIM / 8)
#define B8 (KCOLS * DDIM / 8)
__global__ __launch_bounds__(256)
void convert_kernel(const float* __restrict__ srcA, const float* __restrict__ srcB) {
    const int stride = gridDim.x * blockDim.x;
    for (int i = blockIdx.x * blockDim.x + threadIdx.x; i < A8 + B8; i += 2 * stride) {
#pragma unroll
        for (int u = 0; u < 2; u++) {
            int idx = i + u * stride;
            if (idx >= A8 + B8) break;
            const float4* s4;
            uint4* d4;
            float sc;
            if (idx < A8) {
                s4 = reinterpret_cast<const float4*>(srcA) + (size_t)idx * 2;
                d4 = reinterpret_cast<uint4*>(g_A16) + idx;
                sc = 1.0f;
            } else {
                s4 = reinterpret_cast<const float4*>(srcB) + (size_t)(idx - A8) * 2;
                d4 = reinterpret_cast<uint4*>(g_B16) + (idx - A8);
                sc = BSCALE;
            }
            float4 v0 = s4[0], v1 = s4[1];
            __half2 h[4];
            h[0] = __floats2half2_rn(v0.x * sc, v0.y * sc);
            h[1] = __floats2half2_rn(v0.z * sc, v0.w * sc);
            h[2] = __floats2half2_rn(v1.x * sc, v1.y * sc);
            h[3] = __floats2half2_rn(v1.z * sc, v1.w * sc);
            *d4 = *reinterpret_cast<uint4*>(h);
        }
    }
}

// ---------------------------------------------------------------------------
// fp16 tensor-core GEMM: C[NROWS, KCOLS] = A[NROWS, DDIM] * B[KCOLS, DDIM]^T
// CTA 128x128, 4 warps as 2(M) x 2(N), warp tile 64x64, fp32 accum.
// 2-stage cp.async pipeline, 3 CTAs/SM (stall absorption via occupancy).
// ---------------------------------------------------------------------------
__global__ __launch_bounds__(NTHREADS, 3)
void gemm_tc_kernel(float* __restrict__ C)
{
    extern __shared__ char smem[];
    __shared__ unsigned int sMax[BM];
    const uint32_t smem_base = smem_u32(smem);
    const int tid = threadIdx.x;
    const int lane = tid & 31;
    const int wid = tid >> 5;
    const int wy = wid >> 1;     // 0..1 : M offset wy*64
    const int wx = wid & 1;      // 0..1 : N offset wx*64
    const int bx = blockIdx.x;   // N tile
    const int by = blockIdx.y;   // M tile

    sMax[tid] = 0u;

    const __half* Ab = g_A16 + (size_t)by * BM * DDIM;
    const __half* Bb = g_B16 + (size_t)bx * BN * DDIM;

    const int lrow = tid >> 3;        // 0..15
    const int lc16 = (tid & 7) * 16;  // byte col within 128B row

    float acc[4][8][4];
#pragma unroll
    for (int i = 0; i < 4; i++)
#pragma unroll
        for (int j = 0; j < 8; j++)
#pragma unroll
            for (int q = 0; q < 4; q++) acc[i][j][q] = 0.0f;

    const int rl  = lane & 7;
    const int sel = lane >> 3;
    const int a_row_off = (sel & 1) * 8 + rl;
    const int a_colb    = (sel >> 1) * 16;
    const int b_row_off = (sel >> 1) * 8 + rl;
    const int b_colb    = (sel & 1) * 16;

    auto load_tile = [&](int t) {
        const int s = t & 1;
        const uint32_t sa = smem_base + s * STAGE_BYTES;
        const uint32_t sb = sa + A_BYTES;
        const int d0 = t * BK;
#pragma unroll
        for (int k = 0; k < 8; k++) {
            int r = lrow + k * 16;
            uint32_t off = swz((uint32_t)(r * 128 + lc16));
            CP_ASYNC16(sa + off, Ab + (size_t)r * DDIM + d0 + (lc16 >> 1));
            CP_ASYNC16(sb + off, Bb + (size_t)r * DDIM + d0 + (lc16 >> 1));
        }
        asm volatile("cp.async.commit_group;" ::: "memory");
    };

    load_tile(0);
    load_tile(1);

    for (int t = 0; t < NTILES; t++) {
        if (t < NTILES - 1) asm volatile("cp.async.wait_group 1;" ::: "memory");
        else                asm volatile("cp.async.wait_group 0;" ::: "memory");
        __syncthreads();

        const int s = t & 1;
        const uint32_t sa = smem_base + s * STAGE_BYTES;
        const uint32_t sb = sa + A_BYTES;

        // A fragments double-buffered: LDSM(ks+1) issues under HMMA(ks)
        uint32_t af[2][4][4];
#pragma unroll
        for (int mt = 0; mt < 4; mt++) {
            uint32_t off = (uint32_t)((wy * 64 + mt * 16 + a_row_off) * 128 + a_colb);
            LDSM4(af[0][mt][0], af[0][mt][1], af[0][mt][2], af[0][mt][3], sa + swz(off));
        }

#pragma unroll
        for (int ks = 0; ks < 4; ks++) {        // k step = 16 fp16 = 32B
            const int k0b = ks * 32;
            uint32_t bf[8][2];
#pragma unroll
            for (int p = 0; p < 4; p++) {
                uint32_t off = (uint32_t)((wx * 64 + p * 16 + b_row_off) * 128 +
                                          k0b + b_colb);
                uint32_t r0, r1, r2, r3;
                LDSM4(r0, r1, r2, r3, sb + swz(off));
                bf[p * 2][0] = r0;     bf[p * 2][1] = r1;
                bf[p * 2 + 1][0] = r2; bf[p * 2 + 1][1] = r3;
            }
            if (ks < 3) {
#pragma unroll
                for (int mt = 0; mt < 4; mt++) {
                    uint32_t off = (uint32_t)((wy * 64 + mt * 16 + a_row_off) * 128 +
                                              (ks + 1) * 32 + a_colb);
                    LDSM4(af[(ks + 1) & 1][mt][0], af[(ks + 1) & 1][mt][1],
                          af[(ks + 1) & 1][mt][2], af[(ks + 1) & 1][mt][3],
                          sa + swz(off));
                }
            }
#pragma unroll
            for (int mt = 0; mt < 4; mt++)
#pragma unroll
                for (int nt = 0; nt < 8; nt++)
                    mma_f16(acc[mt][nt], af[ks & 1][mt], bf[nt]);
        }
        __syncthreads();           // stage (t) free before load_tile(t+2) reuses it
        if (t + 2 < NTILES) load_tile(t + 2);
    }

    // ---- epilogue: unscale, write logits + per-row tile max ----
    const int row_base = by * BM + wy * 64 + (lane >> 2);
    const int col_base = bx * BN + wx * 64 + (lane & 3) * 2;
#pragma unroll
    for (int mt = 0; mt < 4; mt++) {
        int r0 = row_base + mt * 16;
        float* C0 = C + (size_t)r0 * KCOLS + col_base;
        float* C1 = C + (size_t)(r0 + 8) * KCOLS + col_base;
        float mx0 = -3.4e38f, mx1 = -3.4e38f;
#pragma unroll
        for (int nt = 0; nt < 8; nt++) {
            float v0 = acc[mt][nt][0] * BSCALE_INV;
            float v1 = acc[mt][nt][1] * BSCALE_INV;
            float v2 = acc[mt][nt][2] * BSCALE_INV;
            float v3 = acc[mt][nt][3] * BSCALE_INV;
            *reinterpret_cast<float2*>(C0 + nt * 8) = make_float2(v0, v1);
            *reinterpret_cast<float2*>(C1 + nt * 8) = make_float2(v2, v3);
            mx0 = fmaxf(mx0, fmaxf(v0, v1));
            mx1 = fmaxf(mx1, fmaxf(v2, v3));
        }
        mx0 = fmaxf(mx0, __shfl_xor_sync(0xffffffffu, mx0, 1));
        mx0 = fmaxf(mx0, __shfl_xor_sync(0xffffffffu, mx0, 2));
        mx1 = fmaxf(mx1, __shfl_xor_sync(0xffffffffu, mx1, 1));
        mx1 = fmaxf(mx1, __shfl_xor_sync(0xffffffffu, mx1, 2));
        if ((lane & 3) == 0) {
            int rl0 = wy * 64 + mt * 16 + (lane >> 2);
            atomicMax(&sMax[rl0],     float_orderable(mx0));
            atomicMax(&sMax[rl0 + 8], float_orderable(mx1));
        }
    }
    __syncthreads();
    g_tilemax[(size_t)(by * BM + tid) * NXTILES + bx] = sMax[tid];
}

// ---------------------------------------------------------------------------
// Exact argmax from tile maxima. Fast path: singleton candidate set is the
// argmax by construction. Slow path (rare): exact fp32 warp-dot recompute.
// ---------------------------------------------------------------------------
__global__ __launch_bounds__(256)
void argmax_kernel(const float* __restrict__ A, const float* __restrict__ B,
                   const float* __restrict__ C, float* __restrict__ out_idx)
{
    __shared__ int sCand[8][20];          // per-warp compacted candidate list
    const int warp_in_blk = threadIdx.x >> 5;
    const int n = (blockIdx.x * blockDim.x + threadIdx.x) >> 5;   // row per warp
    const int lane = threadIdx.x & 31;
    if (n >= NROWS) return;

    // lane t holds tile t's max (NXTILES == 32)
    const unsigned int tm = g_tilemax[(size_t)n * NXTILES + lane];
    unsigned int gm = tm;
#pragma unroll
    for (int off = 16; off; off >>= 1)
        gm = max(gm, __shfl_xor_sync(0xffffffffu, gm, off));

    const float fmx = orderable_to_float(gm);
    const float thr = fmx - 5e-4f;                 // >> 8x worst-case fp16 error
    const unsigned int thr_ord = float_orderable(thr);

    unsigned int tilemask = __ballot_sync(0xffffffffu, tm >= thr_ord);

    const float4* Crow = reinterpret_cast<const float4*>(C + (size_t)n * KCOLS);
    int cand[4];
    int nc = 0;
    while (tilemask) {
        int tile = __ffs(tilemask) - 1;
        tilemask &= tilemask - 1;
        float4 v = Crow[tile * 32 + lane];
        int c0 = tile * BN + lane * 4;
        if (v.x >= thr && nc < 4) cand[nc++] = c0;
        if (v.y >= thr && nc < 4) cand[nc++] = c0 + 1;
        if (v.z >= thr && nc < 4) cand[nc++] = c0 + 2;
        if (v.w >= thr && nc < 4) cand[nc++] = c0 + 3;
    }

    // warp-compact candidates via exclusive prefix over lane counts
    int pfx = nc;
#pragma unroll
    for (int off = 1; off < 32; off <<= 1) {
        int v = __shfl_up_sync(0xffffffffu, pfx, off);
        if (lane >= off) pfx += v;
    }
    int total = __shfl_sync(0xffffffffu, pfx, 31);
    int base = pfx - nc;

    // ---- fast path: singleton candidate set -> it is the argmax ----
    if (total == 1) {
        unsigned int bal = __ballot_sync(0xffffffffu, nc > 0);
        int src = __ffs(bal) - 1;
        int col = __shfl_sync(0xffffffffu, cand[0], src);
        if (lane == 0) out_idx[n] = (float)col;
        return;
    }

    if (total > 20) total = 20;
    for (int j = 0; j < nc; j++) {
        int pos = base + j;
        if (pos < 20) sCand[warp_in_blk][pos] = cand[j];
    }
    __syncwarp();

    // ---- slow path: exact fp32 recompute of all candidates ----
    const float4* z4p = reinterpret_cast<const float4*>(A + (size_t)n * DDIM) + lane * 4;
    float4 za[4];
#pragma unroll
    for (int q = 0; q < 4; q++) za[q] = z4p[q];

    unsigned long long best = 0ULL;
    for (int e = 0; e < total; e++) {
        int col = sCand[warp_in_blk][e];
        const float4* c4 = reinterpret_cast<const float4*>(B + (size_t)col * DDIM) + lane * 4;
        float sum = 0.0f;
#pragma unroll
        for (int q = 0; q < 4; q++) {
            float4 a = za[q], b = c4[q];
            sum = fmaf(a.x, b.x, sum);
            sum = fmaf(a.y, b.y, sum);
            sum = fmaf(a.z, b.z, sum);
            sum = fmaf(a.w, b.w, sum);
        }
#pragma unroll
        for (int off = 16; off; off >>= 1)
            sum += __shfl_xor_sync(0xffffffffu, sum, off);
        unsigned long long p = ((unsigned long long)float_orderable(sum) << 32) |
                               (unsigned int)(KCOLS - 1 - col);   // lower col wins ties
        if (p > best) best = p;
    }
    if (lane == 0)
        out_idx[n] = (float)(KCOLS - 1 - (unsigned int)(best & 0xFFFFFFFFu));
}

extern "C" void kernel_launch(void* const* d_in, const int* in_sizes, int n_in,
                              void* d_out, int out_size) {
    const float* z_e_x    = (const float*)d_in[0];  // [NROWS, DDIM]
    const float* codebook = (const float*)d_in[1];  // [KCOLS, DDIM]
    float* out = (float*)d_out;                      // logits then indices

    cudaFuncSetAttribute(gemm_tc_kernel, cudaFuncAttributeMaxDynamicSharedMemorySize, SMEM_TOTAL);

    convert_kernel<<<1184, 256>>>(z_e_x, codebook);   // 148 SMs * 8 blocks

    dim3 grid(KCOLS / BN, NROWS / BM);   // (32, 256), x fastest -> A-tile L2 reuse
    gemm_tc_kernel<<<grid, NTHREADS, SMEM_TOTAL>>>(out);

    long long logits_elems = (long long)NROWS * KCOLS;
    if ((long long)out_size >= logits_elems + NROWS) {
        argmax_kernel<<<NROWS / 8, 256>>>(z_e_x, codebook, out, out + logits_elems);
    }
}